// round 14
// baseline (speedup 1.0000x reference)
#include <cuda_runtime.h>
#include <cuda_fp16.h>
#include <cstdint>

#define BATCH 2048
#define TSEQ  100
#define DVAR  51
#define HID   128
#define G4    512
#define RPB   28
#define NBLK  74

#define FWT_FLOATS (128*64)

// ---- decoder HMMA smem map (bytes), M=32 ----
#define OFF_A0H   0u          /* 32*200 h = 12800 */
#define OFF_A0L   12800u
#define OFF_A1H   25600u      /* 32*264 h = 16896 */
#define OFF_A1L   42496u
#define OFF_A2H   59392u
#define OFF_A2L   76288u
#define OFF_GATES 93184u      /* 32*520 f32 = 66560 */
#define OFF_C0    159744u     /* 3 * 28*128 f32 = 43008 */
#define OFF_FWTS  202752u     /* 128*52 f32 = 26624 */
#define DEC_SMEM  229376

// ---- encoder rec smem map (bytes), M=32 ----
#define RE_AHI    0u          /* 32*136 h = 8704 */
#define RE_ALO    8704u
#define RE_GATES  17408u      /* 32*520 f32 = 66560 */
#define RE_C      83968u      /* 28*128 f32 = 14336 */
#define RE_BIAS   98304u      /* 512 f32 = 2048 */
#define RE_SMEM   100352

// ---------------- device scratch ----------------
__device__ float  g_fwt[FWT_FLOATS];
__device__ float  g_gx[(size_t)TSEQ*BATCH*G4];
__device__ float  g_hseq[(size_t)TSEQ*BATCH*HID];
__device__ float  g_state[6*BATCH*HID];
__device__ __half g_w16[3*512*128];
__device__ uint2  g_wd[45*2048];          // decoder B-frag pack (+1 pad grp)
__device__ uint2  g_we[3*9*2048];         // encoder Whh B-frag pack (+1 pad)

__device__ __forceinline__ float sigf(float x) {
    return __fdividef(1.0f, 1.0f + __expf(-x));
}
__device__ __forceinline__ float tanhff(float x) {
    float e = __expf(2.0f * x);
    return 1.0f - __fdividef(2.0f, e + 1.0f);
}
__device__ __forceinline__ uint32_t smem_u32(const void* p) {
    uint32_t a;
    asm("{ .reg .u64 t; cvta.to.shared.u64 t, %1; cvt.u32.u64 %0, t; }" : "=r"(a) : "l"(p));
    return a;
}
__device__ __forceinline__ void ldsm4(uint32_t& r0, uint32_t& r1,
                                      uint32_t& r2, uint32_t& r3, uint32_t a) {
    asm volatile("ldmatrix.sync.aligned.m8n8.x4.shared.b16 {%0,%1,%2,%3}, [%4];"
                 : "=r"(r0), "=r"(r1), "=r"(r2), "=r"(r3) : "r"(a));
}
__device__ __forceinline__ void mma16816(float* d,
                                         uint32_t a0, uint32_t a1, uint32_t a2, uint32_t a3,
                                         uint32_t b0, uint32_t b1) {
    asm volatile(
        "mma.sync.aligned.m16n8k16.row.col.f32.f16.f16.f32 "
        "{%0,%1,%2,%3}, {%4,%5,%6,%7}, {%8,%9}, {%0,%1,%2,%3};"
        : "+f"(d[0]), "+f"(d[1]), "+f"(d[2]), "+f"(d[3])
        : "r"(a0), "r"(a1), "r"(a2), "r"(a3), "r"(b0), "r"(b1));
}

// ---------------------------------------------------------------------------
// Prep (unchanged packers, validated)
// ---------------------------------------------------------------------------
__global__ void prep_kernel(
    const float* w0, const float* u0, const float* w1, const float* u1,
    const float* w2, const float* u2, const float* w3, const float* u3,
    const float* w4, const float* u4, const float* w5, const float* u5,
    const float* fW)
{
    const float* WIH[3] = {w0, w1, w2};
    for (int r2 = blockIdx.x*blockDim.x + threadIdx.x; r2 < FWT_FLOATS;
         r2 += gridDim.x*blockDim.x) {
        int u = r2 >> 6;
        int d = r2 & 63;
        g_fwt[r2] = (d < DVAR) ? fW[d*HID + u] : 0.0f;
    }
    const int total2 = 3*512*128;
    for (int idx = blockIdx.x*blockDim.x + threadIdx.x; idx < total2;
         idx += gridDim.x*blockDim.x) {
        int l = idx >> 16;
        int r = idx & 65535;
        int j = r >> 7;
        int k = r & 127;
        int din = (l == 0) ? DVAR : HID;
        g_w16[idx] = __float2half((k < din) ? WIH[l][j*din + k] : 0.0f);
    }
    const int total3 = 45*2048;
    for (int e = blockIdx.x*blockDim.x + threadIdx.x; e < total3;
         e += gridDim.x*blockDim.x) {
        int ksg = e >> 11;
        int r   = e & 2047;
        int n   = r >> 2;
        int q   = r & 3;
        unsigned short h4[4];
#pragma unroll
        for (int i = 0; i < 4; i++) {
            float v = 0.0f;
            if (ksg < 44) {
                int dl, ksl, kin, din;
                if (ksg < 12)      { dl = 0; ksl = ksg;      kin = 64;  din = DVAR; }
                else if (ksg < 28) { dl = 1; ksl = ksg - 12; kin = 128; din = HID; }
                else               { dl = 2; ksl = ksg - 28; kin = 128; din = HID; }
                int k = ksl*16 + q*2 + (i & 1) + ((i >> 1) << 3);
                const float* Wx = (dl == 0) ? w3 : (dl == 1) ? w4 : w5;
                const float* Wh = (dl == 0) ? u3 : (dl == 1) ? u4 : u5;
                if (k < kin) v = (k < din) ? Wx[n*din + k] : 0.0f;
                else         v = Wh[n*HID + (k - kin)];
            }
            h4[i] = __half_as_ushort(__float2half(v));
        }
        uint2 pk;
        pk.x = (uint32_t)h4[0] | ((uint32_t)h4[1] << 16);
        pk.y = (uint32_t)h4[2] | ((uint32_t)h4[3] << 16);
        g_wd[e] = pk;
    }
    const int total4 = 3*9*2048;
    for (int e = blockIdx.x*blockDim.x + threadIdx.x; e < total4;
         e += gridDim.x*blockDim.x) {
        int l   = e / (9*2048);
        int r0  = e - l*(9*2048);
        int ksg = r0 >> 11;
        int r   = r0 & 2047;
        int n   = r >> 2;
        int q   = r & 3;
        const float* Uh = (l == 0) ? u0 : (l == 1) ? u1 : u2;
        unsigned short h4[4];
#pragma unroll
        for (int i = 0; i < 4; i++) {
            float v = 0.0f;
            if (ksg < 8) {
                int k = ksg*16 + q*2 + (i & 1) + ((i >> 1) << 3);
                v = Uh[n*HID + k];
            }
            h4[i] = __half_as_ushort(__float2half(v));
        }
        uint2 pk;
        pk.x = (uint32_t)h4[0] | ((uint32_t)h4[1] << 16);
        pk.y = (uint32_t)h4[2] | ((uint32_t)h4[3] << 16);
        g_we[e] = pk;
    }
}

// ---------------------------------------------------------------------------
// Gx GEMM (HMMA) — unchanged except occupancy 2.
// ---------------------------------------------------------------------------
template<int KT, int MODE>
__global__ void __launch_bounds__(256, 2) gx_kernel(const float* __restrict__ src)
{
    extern __shared__ __half smh[];
    constexpr int SA = KT + 8;
    __half* As = smh;
    __half* Bs = smh + 128*SA;
    const int tid  = threadIdx.x;
    const int wid  = tid >> 5, lane = tid & 31;
    const int nb   = blockIdx.x * 128;
    const int m0   = blockIdx.y * 128;

    for (int idx = tid; idx < 128*KT; idx += 256) {
        int r = idx / KT, k = idx - r*KT;
        float v;
        if (MODE == 0) {
            int m = m0 + r, b = m & (BATCH-1), t = m >> 11;
            v = (k < DVAR) ? src[(b*TSEQ + t)*DVAR + k] : 0.0f;
        } else {
            v = g_hseq[(size_t)(m0 + r)*HID + k];
        }
        As[r*SA + k] = __float2half(v);
    }
    {
        const int L = (MODE == 0) ? 0 : MODE;
        const __half* ws = g_w16 + ((size_t)L*512 + nb)*128;
        for (int idx = tid; idx < 128*KT; idx += 256) {
            int r = idx / KT, k = idx - r*KT;
            Bs[r*SA + k] = ws[r*128 + k];
        }
    }
    __syncthreads();

    float acc[16][4];
#pragma unroll
    for (int i = 0; i < 16; i++)
#pragma unroll
        for (int q = 0; q < 4; q++) acc[i][q] = 0.0f;

    const uint32_t rsel = (lane & 15);
    const uint32_t csel = (uint32_t)(lane >> 4) * 8;
    const uint32_t aaddr = smem_u32(As) + (((uint32_t)wid*16 + rsel)*SA + csel)*2;
    const uint32_t baddr = smem_u32(Bs) + (rsel*SA + csel)*2;

#pragma unroll
    for (int ks = 0; ks < KT/16; ks++) {
        uint32_t a0, a1, a2, a3;
        ldsm4(a0, a1, a2, a3, aaddr + ks*32);
#pragma unroll
        for (int np = 0; np < 8; np++) {
            uint32_t b0, b1, b2, b3;
            ldsm4(b0, b1, b2, b3, baddr + (uint32_t)np*16*SA*2 + ks*32);
            mma16816(acc[2*np    ], a0, a1, a2, a3, b0, b2);
            mma16816(acc[2*np + 1], a0, a1, a2, a3, b1, b3);
        }
    }

    const int mrow = m0 + wid*16 + (lane >> 2);
    float* op  = g_gx + (size_t)mrow*G4 + nb + (lane & 3)*2;
    float* op2 = op + 8*(size_t)G4;
#pragma unroll
    for (int nt = 0; nt < 16; nt++) {
        *(float2*)(op  + nt*8) = make_float2(acc[nt][0], acc[nt][1]);
        *(float2*)(op2 + nt*8) = make_float2(acc[nt][2], acc[nt][3]);
    }
}

// ---------------------------------------------------------------------------
// HMMA GEMM, M=32 (two m16 tiles): gates[32][512] = A(hi+lo) @ B.
// 16 warps, warp w owns 32 cols; B streamed from L2 in fragment order,
// reused across both m-tiles (halves chip L2 weight traffic vs M=16).
// ---------------------------------------------------------------------------
template<int KS, int SA>
__device__ __forceinline__ void gemm32(char* smem, uint32_t ahi_off,
                                       uint32_t alo_off, uint32_t gates_off,
                                       const uint2* __restrict__ wd, int tid)
{
    const int lane  = tid & 31;
    const int wbase = (tid >> 5) * 4;

    float acc[32];
#pragma unroll
    for (int i = 0; i < 32; i++) acc[i] = 0.0f;

    const uint2* bp = wd + wbase*32 + lane;
    uint2 bc[4];
#pragma unroll
    for (int nt = 0; nt < 4; nt++) bc[nt] = bp[nt*32];

    const uint32_t abase = smem_u32(smem) + ((lane & 15)*SA + (lane >> 4)*8)*2;
    const uint32_t ahi0 = abase + ahi_off;
    const uint32_t alo0 = abase + alo_off;
    const uint32_t toff = 16*SA*2;          // second m-tile

#pragma unroll
    for (int ks = 0; ks < KS; ks++) {
        uint2 bn[4];
#pragma unroll
        for (int nt = 0; nt < 4; nt++) bn[nt] = bp[(ks + 1)*2048 + nt*32];
        uint32_t h00, h01, h02, h03, l00, l01, l02, l03;
        uint32_t h10, h11, h12, h13, l10, l11, l12, l13;
        ldsm4(h00, h01, h02, h03, ahi0 + ks*32);
        ldsm4(l00, l01, l02, l03, alo0 + ks*32);
        ldsm4(h10, h11, h12, h13, ahi0 + toff + ks*32);
        ldsm4(l10, l11, l12, l13, alo0 + toff + ks*32);
#pragma unroll
        for (int nt = 0; nt < 4; nt++) {
            float* a0 = acc + nt*8;
            float* a1 = acc + nt*8 + 4;
            mma16816(a0, h00, h01, h02, h03, bc[nt].x, bc[nt].y);
            mma16816(a0, l00, l01, l02, l03, bc[nt].x, bc[nt].y);
            mma16816(a1, h10, h11, h12, h13, bc[nt].x, bc[nt].y);
            mma16816(a1, l10, l11, l12, l13, bc[nt].x, bc[nt].y);
        }
#pragma unroll
        for (int nt = 0; nt < 4; nt++) bc[nt] = bn[nt];
    }

    float* gates = (float*)(smem + gates_off);
    const int row0 = lane >> 2;
    const int colb = wbase*8 + (lane & 3)*2;
#pragma unroll
    for (int nt = 0; nt < 4; nt++)
#pragma unroll
        for (int tile = 0; tile < 2; tile++)
#pragma unroll
            for (int q = 0; q < 2; q++)
                *(float2*)(gates + (row0 + q*8 + tile*16)*520 + colb + nt*8)
                    = make_float2(acc[nt*8 + tile*4 + 2*q], acc[nt*8 + tile*4 + 2*q + 1]);
}

// ---------------------------------------------------------------------------
// Encoder recurrent kernel (HMMA, M=32, 28 rows/CTA).
// ---------------------------------------------------------------------------
__global__ void __launch_bounds__(512, 1) rec_kernel(
    int layer, const float* __restrict__ bias, int writeseq)
{
    extern __shared__ char smem[];
    const int tid = threadIdx.x;
    const int b0  = blockIdx.x * RPB;

    for (int i = tid; i < 4352; i += 512) ((uint32_t*)(smem + RE_AHI))[i] = 0u;
    for (int i = tid; i < 3584; i += 512) ((uint32_t*)(smem + RE_C  ))[i] = 0u;
    ((float*)(smem + RE_BIAS))[tid] = bias[tid];
    __syncthreads();

    const uint2* wd = g_we + layer*9*2048;
    float* gates = (float*)(smem + RE_GATES);
    float* cb    = (float*)(smem + RE_C);
    const float* bias_s = (const float*)(smem + RE_BIAS);

    for (int t = 0; t < TSEQ; t++) {
        gemm32<8, 136>(smem, RE_AHI, RE_ALO, RE_GATES, wd, tid);
        __syncthreads();

#pragma unroll
        for (int it = 0; it < 7; it++) {
            int idx = tid + it*512;
            {
                int r = idx >> 7, u = idx & 127;
                int b = b0 + r; if (b >= BATCH) b = BATCH - 1;
                const float* gx = g_gx + ((size_t)t*BATCH + b)*G4;
                float gi = gates[r*520 + u      ] + bias_s[u      ] + gx[u      ];
                float gf = gates[r*520 + u + 128] + bias_s[u + 128] + gx[u + 128];
                float gg = gates[r*520 + u + 256] + bias_s[u + 256] + gx[u + 256];
                float go = gates[r*520 + u + 384] + bias_s[u + 384] + gx[u + 384];
                float cv = sigf(gf)*cb[r*128 + u] + sigf(gi)*tanhff(gg);
                cb[r*128 + u] = cv;
                float hn = sigf(go)*tanhff(cv);
                __half hh = __float2half(hn);
                __half hl = __float2half(hn - __half2float(hh));
                ((__half*)(smem + RE_AHI))[r*136 + u] = hh;
                ((__half*)(smem + RE_ALO))[r*136 + u] = hl;
                if (writeseq)
                    g_hseq[((size_t)t*BATCH + b)*HID + u] = hn;
                if (t == TSEQ - 1) {
                    g_state[(layer    )*BATCH*HID + b*HID + u] = hn;
                    g_state[(3 + layer)*BATCH*HID + b*HID + u] = cv;
                }
            }
        }
        __syncthreads();
    }
}

// Decoder elementwise for layer L.
template<int L>
__device__ __forceinline__ void dec_ew(char* smem, int tid,
                                       const float* __restrict__ bias)
{
    constexpr int SA_SELF  = (L == 0) ? 200 : 264;
    constexpr int KIN      = (L == 0) ? 64 : 128;
    constexpr uint32_t AHI = (L == 0) ? OFF_A0H : (L == 1) ? OFF_A1H : OFF_A2H;
    constexpr uint32_t ALO = AHI + ((L == 0) ? 12800u : 16896u);
    constexpr uint32_t NHI = (L == 0) ? OFF_A1H : OFF_A2H;
    constexpr uint32_t NLO = NHI + 16896u;

    float* gates = (float*)(smem + OFF_GATES);
    float* cb = (float*)(smem + OFF_C0 + (uint32_t)L*14336u);
#pragma unroll
    for (int it = 0; it < 7; it++) {
        int idx = tid + it*512;
        {
            int r = idx >> 7, u = idx & 127;
            float gi = gates[r*520 + u      ] + __ldg(bias + u      );
            float gf = gates[r*520 + u + 128] + __ldg(bias + u + 128);
            float gg = gates[r*520 + u + 256] + __ldg(bias + u + 256);
            float go = gates[r*520 + u + 384] + __ldg(bias + u + 384);
            float cv = sigf(gf)*cb[r*128 + u] + sigf(gi)*tanhff(gg);
            cb[r*128 + u] = cv;
            float hn = sigf(go)*tanhff(cv);
            __half hh = __float2half(hn);
            __half hl = __float2half(hn - __half2float(hh));
            ((__half*)(smem + AHI))[r*SA_SELF + KIN + u] = hh;
            ((__half*)(smem + ALO))[r*SA_SELF + KIN + u] = hl;
            if (L < 2) {
                ((__half*)(smem + NHI))[r*264 + u] = hh;
                ((__half*)(smem + NLO))[r*264 + u] = hl;
            }
        }
    }
}

// ---------------------------------------------------------------------------
// Decoder persistent kernel (HMMA M=32, 28 rows/CTA).
// ---------------------------------------------------------------------------
__global__ void __launch_bounds__(512, 1) dec_kernel(
    const float* __restrict__ db0, const float* __restrict__ db1,
    const float* __restrict__ db2, const float* __restrict__ fb,
    float* __restrict__ out)
{
    extern __shared__ char smem[];
    const int tid = threadIdx.x;
    const int b0  = blockIdx.x * RPB;

    // zero A buffers (93184 B = 23296 u32)
    for (int i = tid; i < 23296; i += 512)
        ((uint32_t*)(smem + OFF_A0H))[i] = 0u;
    // fwt packed [u][52]
    for (int i = tid; i < 128*52; i += 512) {
        int u = i / 52, d = i - u*52;
        ((float*)(smem + OFF_FWTS))[i] = (d < DVAR) ? g_fwt[(u << 6) + d] : 0.0f;
    }
    __syncthreads();

    // load encoder-final state
    for (int i = tid; i < 3*28*128; i += 512) {
        int u = i & 127;
        int r = (i >> 7) % 28;
        int l = i / (28*128);
        int b = b0 + r; if (b >= BATCH) b = BATCH - 1;
        float hv = g_state[l*BATCH*HID + b*HID + u];
        float cv = g_state[(3 + l)*BATCH*HID + b*HID + u];
        __half hh = __float2half(hv);
        __half hl = __float2half(hv - __half2float(hh));
        uint32_t ahi = (l == 0) ? OFF_A0H : (l == 1) ? OFF_A1H : OFF_A2H;
        uint32_t alo = ahi + ((l == 0) ? 12800u : 16896u);
        int sa  = (l == 0) ? 200 : 264;
        int kin = (l == 0) ? 64 : 128;
        ((__half*)(smem + ahi))[r*sa + kin + u] = hh;
        ((__half*)(smem + alo))[r*sa + kin + u] = hl;
        ((float*)(smem + OFF_C0 + (uint32_t)l*14336u))[r*128 + u] = cv;
    }
    __syncthreads();

    const float* fwts = (const float*)(smem + OFF_FWTS);
    const __half* h2h = (const __half*)(smem + OFF_A2H);
    const __half* h2l = (const __half*)(smem + OFF_A2L);

    for (int t = 0; t < TSEQ; t++) {
        gemm32<12, 200>(smem, OFF_A0H, OFF_A0L, OFF_GATES, g_wd,           tid);
        __syncthreads();
        dec_ew<0>(smem, tid, db0);
        __syncthreads();
        gemm32<16, 264>(smem, OFF_A1H, OFF_A1L, OFF_GATES, g_wd + 12*2048, tid);
        __syncthreads();
        dec_ew<1>(smem, tid, db1);
        __syncthreads();
        gemm32<16, 264>(smem, OFF_A2H, OFF_A2L, OFF_GATES, g_wd + 28*2048, tid);
        __syncthreads();
        dec_ew<2>(smem, tid, db2);
        __syncthreads();

        // head: pred = h2 @ fW^T + fb (h2 reconstructed from A2 hi+lo)
        {
            int d  = tid & 63;
            int rg = tid >> 6;
            float fbv = (d < DVAR) ? __ldg(fb + d) : 0.0f;
            float a[4];
#pragma unroll
            for (int q = 0; q < 4; q++) a[q] = fbv;
            int dd = (d < DVAR) ? d : 0;
#pragma unroll 4
            for (int u = 0; u < HID; u++) {
                float wv = fwts[u*52 + dd];
#pragma unroll
                for (int q = 0; q < 3; q++) {
                    int r = rg + q*8;
                    float hv = __half2float(h2h[r*264 + 128 + u])
                             + __half2float(h2l[r*264 + 128 + u]);
                    a[q] += hv * wv;
                }
                if (rg < 4) {
                    int r = rg + 24;
                    float hv = __half2float(h2h[r*264 + 128 + u])
                             + __half2float(h2l[r*264 + 128 + u]);
                    a[3] += hv * wv;
                }
            }
            if (d < DVAR) {
                __half* xh = (__half*)(smem + OFF_A0H);
                __half* xl = (__half*)(smem + OFF_A0L);
#pragma unroll
                for (int q = 0; q < 4; q++) {
                    int r = rg + q*8;
                    if (r < RPB) {
                        __half p = __float2half(a[q]);
                        xh[r*200 + d] = p;
                        xl[r*200 + d] = __float2half(a[q] - __half2float(p));
                        int bb = b0 + r;
                        if (bb < BATCH)
                            out[(bb*TSEQ + (TSEQ - 1 - t))*DVAR + d] = a[q];
                    }
                }
            }
        }
        __syncthreads();
    }
}

// ---------------------------------------------------------------------------
extern "C" void kernel_launch(void* const* d_in, const int* in_sizes, int n_in,
                              void* d_out, int out_size)
{
    const float* src = (const float*)d_in[0];
    const float* eW0 = (const float*)d_in[1];
    const float* eU0 = (const float*)d_in[2];
    const float* eb0 = (const float*)d_in[3];
    const float* eW1 = (const float*)d_in[4];
    const float* eU1 = (const float*)d_in[5];
    const float* eb1 = (const float*)d_in[6];
    const float* eW2 = (const float*)d_in[7];
    const float* eU2 = (const float*)d_in[8];
    const float* eb2 = (const float*)d_in[9];
    const float* dW0 = (const float*)d_in[10];
    const float* dU0 = (const float*)d_in[11];
    const float* db0 = (const float*)d_in[12];
    const float* dW1 = (const float*)d_in[13];
    const float* dU1 = (const float*)d_in[14];
    const float* db1 = (const float*)d_in[15];
    const float* dW2 = (const float*)d_in[16];
    const float* dU2 = (const float*)d_in[17];
    const float* db2 = (const float*)d_in[18];
    const float* fW  = (const float*)d_in[19];
    const float* fb  = (const float*)d_in[20];
    float* out = (float*)d_out;

    const int GX64_SMEM  = 2*128*(64 + 8)*2;
    const int GX128_SMEM = 2*128*(128 + 8)*2;

    cudaFuncSetAttribute(gx_kernel<64,0>,  cudaFuncAttributeMaxDynamicSharedMemorySize, GX64_SMEM);
    cudaFuncSetAttribute(gx_kernel<128,1>, cudaFuncAttributeMaxDynamicSharedMemorySize, GX128_SMEM);
    cudaFuncSetAttribute(gx_kernel<128,2>, cudaFuncAttributeMaxDynamicSharedMemorySize, GX128_SMEM);
    cudaFuncSetAttribute(rec_kernel, cudaFuncAttributeMaxDynamicSharedMemorySize, RE_SMEM);
    cudaFuncSetAttribute(dec_kernel, cudaFuncAttributeMaxDynamicSharedMemorySize, DEC_SMEM);

    prep_kernel<<<1024, 256>>>(eW0, eU0, eW1, eU1, eW2, eU2,
                               dW0, dU0, dW1, dU1, dW2, dU2, fW);

    dim3 gxgrid(4, 1600);
    gx_kernel<64,0><<<gxgrid, 256, GX64_SMEM>>>(src);
    rec_kernel<<<NBLK, 512, RE_SMEM>>>(0, eb0, 1);
    gx_kernel<128,1><<<gxgrid, 256, GX128_SMEM>>>(src);
    rec_kernel<<<NBLK, 512, RE_SMEM>>>(1, eb1, 1);
    gx_kernel<128,2><<<gxgrid, 256, GX128_SMEM>>>(src);
    rec_kernel<<<NBLK, 512, RE_SMEM>>>(2, eb2, 0);
    dec_kernel<<<NBLK, 512, DEC_SMEM>>>(db0, db1, db2, fb, out);
}

// round 15
// speedup vs baseline: 1.8763x; 1.8763x over previous
#include <cuda_runtime.h>
#include <cuda_fp16.h>
#include <cstdint>

#define BATCH 2048
#define TSEQ  100
#define DVAR  51
#define HID   128
#define G4    512
#define RPB   14
#define NBLK  147

#define FWT_FLOATS (128*64)

// ---- decoder HMMA smem map (bytes) ----
#define OFF_FWT   0u
#define OFF_BIAS  32768u
#define OFF_A0H   38912u
#define OFF_A0L   45312u
#define OFF_A1H   51712u
#define OFF_A1L   60160u
#define OFF_A2H   68608u
#define OFF_A2L   77056u
#define OFF_GATES 85504u
#define OFF_C0    118784u
#define OFF_H2    144128u
#define DEC_SMEM  152576

// ---- encoder rec HMMA smem map (bytes) ----
#define RE_AHI    0u
#define RE_ALO    4352u
#define RE_GATES  8704u
#define RE_C      41984u
#define RE_BIAS   50432u
#define RE_SMEM   52480

// ---------------- device scratch ----------------
__device__ float  g_fwt[FWT_FLOATS];
__device__ __half g_gx[(size_t)TSEQ*BATCH*G4];        // fp16: halves gx write + rec read traffic
__device__ __half g_hseq[(size_t)TSEQ*BATCH*HID];     // fp16: gx consumes fp16 anyway
__device__ float  g_state[6*BATCH*HID];
__device__ __half g_w16[3*512*128];
__device__ uint2  g_wd[45*2048];
__device__ uint2  g_we[3*9*2048];

__device__ __forceinline__ float sigf(float x) {
    return __fdividef(1.0f, 1.0f + __expf(-x));
}
__device__ __forceinline__ float tanhff(float x) {
    float e = __expf(2.0f * x);
    return 1.0f - __fdividef(2.0f, e + 1.0f);
}
__device__ __forceinline__ uint32_t smem_u32(const void* p) {
    uint32_t a;
    asm("{ .reg .u64 t; cvta.to.shared.u64 t, %1; cvt.u32.u64 %0, t; }" : "=r"(a) : "l"(p));
    return a;
}
__device__ __forceinline__ void ldsm4(uint32_t& r0, uint32_t& r1,
                                      uint32_t& r2, uint32_t& r3, uint32_t a) {
    asm volatile("ldmatrix.sync.aligned.m8n8.x4.shared.b16 {%0,%1,%2,%3}, [%4];"
                 : "=r"(r0), "=r"(r1), "=r"(r2), "=r"(r3) : "r"(a));
}
__device__ __forceinline__ void mma16816(float* d,
                                         uint32_t a0, uint32_t a1, uint32_t a2, uint32_t a3,
                                         uint32_t b0, uint32_t b1) {
    asm volatile(
        "mma.sync.aligned.m16n8k16.row.col.f32.f16.f16.f32 "
        "{%0,%1,%2,%3}, {%4,%5,%6,%7}, {%8,%9}, {%0,%1,%2,%3};"
        : "+f"(d[0]), "+f"(d[1]), "+f"(d[2]), "+f"(d[3])
        : "r"(a0), "r"(a1), "r"(a2), "r"(a3), "r"(b0), "r"(b1));
}

// ---------------------------------------------------------------------------
// Prep: fW^T, fp16 Wih images (gx), decoder + encoder B-fragment packs.
// ---------------------------------------------------------------------------
__global__ void prep_kernel(
    const float* w0, const float* u0, const float* w1, const float* u1,
    const float* w2, const float* u2, const float* w3, const float* u3,
    const float* w4, const float* u4, const float* w5, const float* u5,
    const float* fW)
{
    const float* WIH[3] = {w0, w1, w2};
    for (int r2 = blockIdx.x*blockDim.x + threadIdx.x; r2 < FWT_FLOATS;
         r2 += gridDim.x*blockDim.x) {
        int u = r2 >> 6;
        int d = r2 & 63;
        g_fwt[r2] = (d < DVAR) ? fW[d*HID + u] : 0.0f;
    }
    const int total2 = 3*512*128;
    for (int idx = blockIdx.x*blockDim.x + threadIdx.x; idx < total2;
         idx += gridDim.x*blockDim.x) {
        int l = idx >> 16;
        int r = idx & 65535;
        int j = r >> 7;
        int k = r & 127;
        int din = (l == 0) ? DVAR : HID;
        g_w16[idx] = __float2half((k < din) ? WIH[l][j*din + k] : 0.0f);
    }
    const int total3 = 45*2048;
    for (int e = blockIdx.x*blockDim.x + threadIdx.x; e < total3;
         e += gridDim.x*blockDim.x) {
        int ksg = e >> 11;
        int r   = e & 2047;
        int n   = r >> 2;
        int q   = r & 3;
        unsigned short h4[4];
#pragma unroll
        for (int i = 0; i < 4; i++) {
            float v = 0.0f;
            if (ksg < 44) {
                int dl, ksl, kin, din;
                if (ksg < 12)      { dl = 0; ksl = ksg;      kin = 64;  din = DVAR; }
                else if (ksg < 28) { dl = 1; ksl = ksg - 12; kin = 128; din = HID; }
                else               { dl = 2; ksl = ksg - 28; kin = 128; din = HID; }
                int k = ksl*16 + q*2 + (i & 1) + ((i >> 1) << 3);
                const float* Wx = (dl == 0) ? w3 : (dl == 1) ? w4 : w5;
                const float* Wh = (dl == 0) ? u3 : (dl == 1) ? u4 : u5;
                if (k < kin) v = (k < din) ? Wx[n*din + k] : 0.0f;
                else         v = Wh[n*HID + (k - kin)];
            }
            h4[i] = __half_as_ushort(__float2half(v));
        }
        uint2 pk;
        pk.x = (uint32_t)h4[0] | ((uint32_t)h4[1] << 16);
        pk.y = (uint32_t)h4[2] | ((uint32_t)h4[3] << 16);
        g_wd[e] = pk;
    }
    const int total4 = 3*9*2048;
    for (int e = blockIdx.x*blockDim.x + threadIdx.x; e < total4;
         e += gridDim.x*blockDim.x) {
        int l   = e / (9*2048);
        int r0  = e - l*(9*2048);
        int ksg = r0 >> 11;
        int r   = r0 & 2047;
        int n   = r >> 2;
        int q   = r & 3;
        const float* Uh = (l == 0) ? u0 : (l == 1) ? u1 : u2;
        unsigned short h4[4];
#pragma unroll
        for (int i = 0; i < 4; i++) {
            float v = 0.0f;
            if (ksg < 8) {
                int k = ksg*16 + q*2 + (i & 1) + ((i >> 1) << 3);
                v = Uh[n*HID + k];
            }
            h4[i] = __half_as_ushort(__float2half(v));
        }
        uint2 pk;
        pk.x = (uint32_t)h4[0] | ((uint32_t)h4[1] << 16);
        pk.y = (uint32_t)h4[2] | ((uint32_t)h4[3] << 16);
        g_we[e] = pk;
    }
}

// ---------------------------------------------------------------------------
// Gx GEMM (HMMA): fp16 in/out. A from src (MODE 0, cvt) or g_hseq (fp16 copy).
// ---------------------------------------------------------------------------
template<int KT, int MODE>
__global__ void __launch_bounds__(256, 2) gx_kernel(const float* __restrict__ src)
{
    extern __shared__ __half smh[];
    constexpr int SA = KT + 8;
    __half* As = smh;
    __half* Bs = smh + 128*SA;
    const int tid  = threadIdx.x;
    const int wid  = tid >> 5, lane = tid & 31;
    const int nb   = blockIdx.x * 128;
    const int m0   = blockIdx.y * 128;

    if (MODE == 0) {
        for (int idx = tid; idx < 128*KT; idx += 256) {
            int r = idx / KT, k = idx - r*KT;
            int m = m0 + r, b = m & (BATCH-1), t = m >> 11;
            float v = (k < DVAR) ? src[(b*TSEQ + t)*DVAR + k] : 0.0f;
            As[r*SA + k] = __float2half(v);
        }
    } else {
        // vectorized fp16 copy: 8 halves per uint4
        for (int idx = tid; idx < 128*(KT/8); idx += 256) {
            int r  = idx / (KT/8);
            int k8 = idx - r*(KT/8);
            uint4 v = *(const uint4*)(g_hseq + (size_t)(m0 + r)*HID + k8*8);
            *(uint4*)(As + r*SA + k8*8) = v;
        }
    }
    {
        const int L = (MODE == 0) ? 0 : MODE;
        const uint4* ws = (const uint4*)(g_w16 + ((size_t)L*512 + nb)*128);
        for (int idx = tid; idx < 128*(KT/8); idx += 256) {
            int r  = idx / (KT/8);
            int k8 = idx - r*(KT/8);
            *(uint4*)(Bs + r*SA + k8*8) = ws[r*16 + k8];
        }
    }
    __syncthreads();

    float acc[16][4];
#pragma unroll
    for (int i = 0; i < 16; i++)
#pragma unroll
        for (int q = 0; q < 4; q++) acc[i][q] = 0.0f;

    const uint32_t rsel = (lane & 15);
    const uint32_t csel = (uint32_t)(lane >> 4) * 8;
    const uint32_t aaddr = smem_u32(As) + (((uint32_t)wid*16 + rsel)*SA + csel)*2;
    const uint32_t baddr = smem_u32(Bs) + (rsel*SA + csel)*2;

#pragma unroll
    for (int ks = 0; ks < KT/16; ks++) {
        uint32_t a0, a1, a2, a3;
        ldsm4(a0, a1, a2, a3, aaddr + ks*32);
#pragma unroll
        for (int np = 0; np < 8; np++) {
            uint32_t b0, b1, b2, b3;
            ldsm4(b0, b1, b2, b3, baddr + (uint32_t)np*16*SA*2 + ks*32);
            mma16816(acc[2*np    ], a0, a1, a2, a3, b0, b2);
            mma16816(acc[2*np + 1], a0, a1, a2, a3, b1, b3);
        }
    }

    const int mrow = m0 + wid*16 + (lane >> 2);
    __half* op  = g_gx + (size_t)mrow*G4 + nb + (lane & 3)*2;
    __half* op2 = op + 8*(size_t)G4;
#pragma unroll
    for (int nt = 0; nt < 16; nt++) {
        *(__half2*)(op  + nt*8) = __floats2half2_rn(acc[nt][0], acc[nt][1]);
        *(__half2*)(op2 + nt*8) = __floats2half2_rn(acc[nt][2], acc[nt][3]);
    }
}

// ---------------------------------------------------------------------------
// HMMA GEMM (M=16): gates[16][512] = A(hi+lo)@B, B streamed from L2.
// ---------------------------------------------------------------------------
template<int KS, int SA>
__device__ __forceinline__ void dec_gemm(char* smem, uint32_t ahi_off,
                                         uint32_t alo_off, uint32_t gates_off,
                                         const uint2* __restrict__ wd, int tid)
{
    const int lane  = tid & 31;
    const int wbase = (tid >> 5) * 4;

    float acc[16];
#pragma unroll
    for (int i = 0; i < 16; i++) acc[i] = 0.0f;

    const uint2* bp = wd + wbase*32 + lane;
    uint2 bc[4];
#pragma unroll
    for (int nt = 0; nt < 4; nt++) bc[nt] = bp[nt*32];

    const uint32_t abase = smem_u32(smem) + ((lane & 15)*SA + (lane >> 4)*8)*2;
    const uint32_t ahi = abase + ahi_off;
    const uint32_t alo = abase + alo_off;

#pragma unroll
    for (int ks = 0; ks < KS; ks++) {
        uint2 bn[4];
#pragma unroll
        for (int nt = 0; nt < 4; nt++) bn[nt] = bp[(ks + 1)*2048 + nt*32];
        uint32_t ah0, ah1, ah2, ah3, al0, al1, al2, al3;
        ldsm4(ah0, ah1, ah2, ah3, ahi + ks*32);
        ldsm4(al0, al1, al2, al3, alo + ks*32);
#pragma unroll
        for (int nt = 0; nt < 4; nt++) {
            mma16816(acc + nt*4, ah0, ah1, ah2, ah3, bc[nt].x, bc[nt].y);
            mma16816(acc + nt*4, al0, al1, al2, al3, bc[nt].x, bc[nt].y);
        }
#pragma unroll
        for (int nt = 0; nt < 4; nt++) bc[nt] = bn[nt];
    }

    float* gates = (float*)(smem + gates_off);
    const int row0 = lane >> 2;
    const int colb = wbase*8 + (lane & 3)*2;
#pragma unroll
    for (int nt = 0; nt < 4; nt++)
#pragma unroll
        for (int q = 0; q < 2; q++)
            *(float2*)(gates + (row0 + q*8)*520 + colb + nt*8)
                = make_float2(acc[nt*4 + 2*q], acc[nt*4 + 2*q + 1]);
}

// ---------------------------------------------------------------------------
// Encoder recurrent kernel (HMMA, M=16, 14 rows/CTA, 147 CTAs).
// ---------------------------------------------------------------------------
__global__ void __launch_bounds__(512, 1) rec_kernel(
    int layer, const float* __restrict__ bias, int writeseq)
{
    extern __shared__ char smem[];
    const int tid = threadIdx.x;
    const int b0  = blockIdx.x * RPB;

    for (int i = tid; i < 2176; i += 512) ((uint32_t*)(smem + RE_AHI))[i] = 0u;
    for (int i = tid; i < 2112; i += 512) ((uint32_t*)(smem + RE_C  ))[i] = 0u;
    ((float*)(smem + RE_BIAS))[tid] = bias[tid];
    __syncthreads();

    const uint2* wd = g_we + layer*9*2048;
    float* gates = (float*)(smem + RE_GATES);
    float* cb    = (float*)(smem + RE_C);
    const float* bias_s = (const float*)(smem + RE_BIAS);

    for (int t = 0; t < TSEQ; t++) {
        dec_gemm<8, 136>(smem, RE_AHI, RE_ALO, RE_GATES, wd, tid);
        __syncthreads();

#pragma unroll
        for (int it = 0; it < 4; it++) {
            int idx = tid + it*512;
            if (idx < 14*128) {
                int r = idx >> 7, u = idx & 127;
                int b = b0 + r; if (b >= BATCH) b = BATCH - 1;
                const __half* gx = g_gx + ((size_t)t*BATCH + b)*G4;
                float gi = gates[r*520 + u      ] + bias_s[u      ] + __half2float(gx[u      ]);
                float gf = gates[r*520 + u + 128] + bias_s[u + 128] + __half2float(gx[u + 128]);
                float gg = gates[r*520 + u + 256] + bias_s[u + 256] + __half2float(gx[u + 256]);
                float go = gates[r*520 + u + 384] + bias_s[u + 384] + __half2float(gx[u + 384]);
                float cv = sigf(gf)*cb[r*132 + u] + sigf(gi)*tanhff(gg);
                cb[r*132 + u] = cv;
                float hn = sigf(go)*tanhff(cv);
                __half hh = __float2half(hn);
                __half hl = __float2half(hn - __half2float(hh));
                ((__half*)(smem + RE_AHI))[r*136 + u] = hh;
                ((__half*)(smem + RE_ALO))[r*136 + u] = hl;
                if (writeseq)
                    g_hseq[((size_t)t*BATCH + b)*HID + u] = hh;
                if (t == TSEQ - 1) {
                    g_state[(layer    )*BATCH*HID + b*HID + u] = hn;
                    g_state[(3 + layer)*BATCH*HID + b*HID + u] = cv;
                }
            }
        }
        __syncthreads();
    }
}

// Decoder elementwise for layer L (validated).
template<int L>
__device__ __forceinline__ void dec_ew(char* smem, int tid)
{
    constexpr int SA_SELF  = (L == 0) ? 200 : 264;
    constexpr int KIN      = (L == 0) ? 64 : 128;
    constexpr uint32_t AHI = (L == 0) ? OFF_A0H : (L == 1) ? OFF_A1H : OFF_A2H;
    constexpr uint32_t ALO = AHI + ((L == 0) ? 6400u : 8448u);
    constexpr uint32_t NHI = (L == 0) ? OFF_A1H : OFF_A2H;
    constexpr uint32_t NLO = NHI + 8448u;

    float* gates = (float*)(smem + OFF_GATES);
    const float* bias = (const float*)(smem + OFF_BIAS) + L*512;
    float* cb = (float*)(smem + OFF_C0 + L*8448u);
#pragma unroll
    for (int it = 0; it < 4; it++) {
        int idx = tid + it*512;
        if (idx < 14*128) {
            int r = idx >> 7, u = idx & 127;
            float gi = gates[r*520 + u      ] + bias[u      ];
            float gf = gates[r*520 + u + 128] + bias[u + 128];
            float gg = gates[r*520 + u + 256] + bias[u + 256];
            float go = gates[r*520 + u + 384] + bias[u + 384];
            float cv = sigf(gf)*cb[r*132 + u] + sigf(gi)*tanhff(gg);
            cb[r*132 + u] = cv;
            float hn = sigf(go)*tanhff(cv);
            __half hh = __float2half(hn);
            __half hl = __float2half(hn - __half2float(hh));
            ((__half*)(smem + AHI))[r*SA_SELF + KIN + u] = hh;
            ((__half*)(smem + ALO))[r*SA_SELF + KIN + u] = hl;
            if (L < 2) {
                ((__half*)(smem + NHI))[r*264 + u] = hh;
                ((__half*)(smem + NLO))[r*264 + u] = hl;
            } else {
                ((float*)(smem + OFF_H2))[r*132 + u] = hn;
            }
        }
    }
}

// ---------------------------------------------------------------------------
// Decoder persistent kernel (validated R13 version).
// ---------------------------------------------------------------------------
__global__ void __launch_bounds__(512, 1) dec_kernel(
    const float* __restrict__ db0, const float* __restrict__ db1,
    const float* __restrict__ db2, const float* __restrict__ fb,
    float* __restrict__ out)
{
    extern __shared__ char smem[];
    const int tid = threadIdx.x;
    const int b0  = blockIdx.x * RPB;

    for (int i = tid; i < 11648; i += 512)
        ((uint32_t*)(smem + OFF_A0H))[i] = 0u;
    for (int i = tid; i < FWT_FLOATS; i += 512)
        ((float*)(smem + OFF_FWT))[i] = g_fwt[i];
    {
        float* bias = (float*)(smem + OFF_BIAS);
        bias[tid]        = db0[tid];
        bias[512 + tid]  = db1[tid];
        bias[1024 + tid] = db2[tid];
    }
    __syncthreads();

    for (int i = tid; i < 3*14*128; i += 512) {
        int u = i & 127;
        int r = (i >> 7) % 14;
        int l = i / (14*128);
        int b = b0 + r; if (b >= BATCH) b = BATCH - 1;
        float hv = g_state[l*BATCH*HID + b*HID + u];
        float cv = g_state[(3 + l)*BATCH*HID + b*HID + u];
        __half hh = __float2half(hv);
        __half hl = __float2half(hv - __half2float(hh));
        uint32_t ahi = (l == 0) ? OFF_A0H : (l == 1) ? OFF_A1H : OFF_A2H;
        uint32_t alo = ahi + ((l == 0) ? 6400u : 8448u);
        int sa  = (l == 0) ? 200 : 264;
        int kin = (l == 0) ? 64 : 128;
        ((__half*)(smem + ahi))[r*sa + kin + u] = hh;
        ((__half*)(smem + alo))[r*sa + kin + u] = hl;
        ((float*)(smem + OFF_C0 + (uint32_t)l*8448u))[r*132 + u] = cv;
    }
    __syncthreads();

    const float* fwts = (const float*)(smem + OFF_FWT);

    for (int t = 0; t < TSEQ; t++) {
        dec_gemm<12, 200>(smem, OFF_A0H, OFF_A0L, OFF_GATES, g_wd,           tid);
        __syncthreads();
        dec_ew<0>(smem, tid);
        __syncthreads();
        dec_gemm<16, 264>(smem, OFF_A1H, OFF_A1L, OFF_GATES, g_wd + 12*2048, tid);
        __syncthreads();
        dec_ew<1>(smem, tid);
        __syncthreads();
        dec_gemm<16, 264>(smem, OFF_A2H, OFF_A2L, OFF_GATES, g_wd + 28*2048, tid);
        __syncthreads();
        dec_ew<2>(smem, tid);
        __syncthreads();

        {
            int d  = tid & 63;
            int rg = tid >> 6;
            const float* h2 = (const float*)(smem + OFF_H2);
            float fbv = (d < DVAR) ? fb[d] : 0.0f;
            float a0 = fbv, a1 = fbv;
            int r0 = rg, r1 = rg + 8;
#pragma unroll 4
            for (int u = 0; u < HID; u++) {
                float wv = fwts[(u << 6) + d];
                a0 += h2[r0*132 + u] * wv;
                a1 += h2[r1*132 + u] * wv;
            }
            if (d < DVAR) {
                __half* xh = (__half*)(smem + OFF_A0H);
                __half* xl = (__half*)(smem + OFF_A0L);
                __half p0 = __float2half(a0);
                xh[r0*200 + d] = p0;
                xl[r0*200 + d] = __float2half(a0 - __half2float(p0));
                int bb = b0 + r0;
                if (bb < BATCH)
                    out[(bb*TSEQ + (TSEQ - 1 - t))*DVAR + d] = a0;
                if (r1 < RPB) {
                    __half p1 = __float2half(a1);
                    xh[r1*200 + d] = p1;
                    xl[r1*200 + d] = __float2half(a1 - __half2float(p1));
                    int bb1 = b0 + r1;
                    if (bb1 < BATCH)
                        out[(bb1*TSEQ + (TSEQ - 1 - t))*DVAR + d] = a1;
                }
            }
        }
        __syncthreads();
    }
}

// ---------------------------------------------------------------------------
extern "C" void kernel_launch(void* const* d_in, const int* in_sizes, int n_in,
                              void* d_out, int out_size)
{
    const float* src = (const float*)d_in[0];
    const float* eW0 = (const float*)d_in[1];
    const float* eU0 = (const float*)d_in[2];
    const float* eb0 = (const float*)d_in[3];
    const float* eW1 = (const float*)d_in[4];
    const float* eU1 = (const float*)d_in[5];
    const float* eb1 = (const float*)d_in[6];
    const float* eW2 = (const float*)d_in[7];
    const float* eU2 = (const float*)d_in[8];
    const float* eb2 = (const float*)d_in[9];
    const float* dW0 = (const float*)d_in[10];
    const float* dU0 = (const float*)d_in[11];
    const float* db0 = (const float*)d_in[12];
    const float* dW1 = (const float*)d_in[13];
    const float* dU1 = (const float*)d_in[14];
    const float* db1 = (const float*)d_in[15];
    const float* dW2 = (const float*)d_in[16];
    const float* dU2 = (const float*)d_in[17];
    const float* db2 = (const float*)d_in[18];
    const float* fW  = (const float*)d_in[19];
    const float* fb  = (const float*)d_in[20];
    float* out = (float*)d_out;

    const int GX64_SMEM  = 2*128*(64 + 8)*2;
    const int GX128_SMEM = 2*128*(128 + 8)*2;

    cudaFuncSetAttribute(gx_kernel<64,0>,  cudaFuncAttributeMaxDynamicSharedMemorySize, GX64_SMEM);
    cudaFuncSetAttribute(gx_kernel<128,1>, cudaFuncAttributeMaxDynamicSharedMemorySize, GX128_SMEM);
    cudaFuncSetAttribute(gx_kernel<128,2>, cudaFuncAttributeMaxDynamicSharedMemorySize, GX128_SMEM);
    cudaFuncSetAttribute(rec_kernel, cudaFuncAttributeMaxDynamicSharedMemorySize, RE_SMEM);
    cudaFuncSetAttribute(dec_kernel, cudaFuncAttributeMaxDynamicSharedMemorySize, DEC_SMEM);

    prep_kernel<<<1024, 256>>>(eW0, eU0, eW1, eU1, eW2, eU2,
                               dW0, dU0, dW1, dU1, dW2, dU2, fW);

    dim3 gxgrid(4, 1600);
    gx_kernel<64,0><<<gxgrid, 256, GX64_SMEM>>>(src);
    rec_kernel<<<NBLK, 512, RE_SMEM>>>(0, eb0, 1);
    gx_kernel<128,1><<<gxgrid, 256, GX128_SMEM>>>(src);
    rec_kernel<<<NBLK, 512, RE_SMEM>>>(1, eb1, 1);
    gx_kernel<128,2><<<gxgrid, 256, GX128_SMEM>>>(src);
    rec_kernel<<<NBLK, 512, RE_SMEM>>>(2, eb2, 0);
    dec_kernel<<<NBLK, 512, DEC_SMEM>>>(db0, db1, db2, fb, out);
}

// round 16
// speedup vs baseline: 1.9466x; 1.0375x over previous
#include <cuda_runtime.h>
#include <cuda_fp16.h>
#include <cstdint>

#define BATCH 2048
#define TSEQ  100
#define DVAR  51
#define HID   128
#define G4    512
#define RPB   14
#define NBLK  147

#define FWT_FLOATS (128*64)

// ---- decoder HMMA smem map (bytes) ----
#define OFF_FWT   0u
#define OFF_BIAS  32768u
#define OFF_A0H   38912u
#define OFF_A0L   45312u
#define OFF_A1H   51712u
#define OFF_A1L   60160u
#define OFF_A2H   68608u
#define OFF_A2L   77056u
#define OFF_GATES 85504u
#define OFF_C0    118784u
#define OFF_H2    144128u
#define DEC_SMEM  152576

// ---- encoder rec HMMA smem map (bytes) ----
#define RE_AHI    0u
#define RE_ALO    4352u
#define RE_GATES  8704u
#define RE_C      41984u
#define RE_BIAS   50432u
#define RE_SMEM   52480

// ---------------- device scratch ----------------
__device__ float  g_fwt[FWT_FLOATS];
__device__ __half g_gx[(size_t)TSEQ*BATCH*G4];
__device__ __half g_hseq[(size_t)TSEQ*BATCH*HID];
__device__ float  g_state[6*BATCH*HID];
__device__ __half g_w16[3*512*128];
__device__ uint2  g_wd[45*2048];
__device__ uint2  g_we[3*9*2048];

__device__ __forceinline__ float sigf(float x) {
    return __fdividef(1.0f, 1.0f + __expf(-x));
}
__device__ __forceinline__ float tanhff(float x) {
    float e = __expf(2.0f * x);
    return 1.0f - __fdividef(2.0f, e + 1.0f);
}
__device__ __forceinline__ uint32_t smem_u32(const void* p) {
    uint32_t a;
    asm("{ .reg .u64 t; cvta.to.shared.u64 t, %1; cvt.u32.u64 %0, t; }" : "=r"(a) : "l"(p));
    return a;
}
__device__ __forceinline__ void ldsm4(uint32_t& r0, uint32_t& r1,
                                      uint32_t& r2, uint32_t& r3, uint32_t a) {
    asm volatile("ldmatrix.sync.aligned.m8n8.x4.shared.b16 {%0,%1,%2,%3}, [%4];"
                 : "=r"(r0), "=r"(r1), "=r"(r2), "=r"(r3) : "r"(a));
}
__device__ __forceinline__ void mma16816(float* d,
                                         uint32_t a0, uint32_t a1, uint32_t a2, uint32_t a3,
                                         uint32_t b0, uint32_t b1) {
    asm volatile(
        "mma.sync.aligned.m16n8k16.row.col.f32.f16.f16.f32 "
        "{%0,%1,%2,%3}, {%4,%5,%6,%7}, {%8,%9}, {%0,%1,%2,%3};"
        : "+f"(d[0]), "+f"(d[1]), "+f"(d[2]), "+f"(d[3])
        : "r"(a0), "r"(a1), "r"(a2), "r"(a3), "r"(b0), "r"(b1));
}

// ---------------------------------------------------------------------------
// Prep (validated packers, unchanged)
// ---------------------------------------------------------------------------
__global__ void prep_kernel(
    const float* w0, const float* u0, const float* w1, const float* u1,
    const float* w2, const float* u2, const float* w3, const float* u3,
    const float* w4, const float* u4, const float* w5, const float* u5,
    const float* fW)
{
    const float* WIH[3] = {w0, w1, w2};
    for (int r2 = blockIdx.x*blockDim.x + threadIdx.x; r2 < FWT_FLOATS;
         r2 += gridDim.x*blockDim.x) {
        int u = r2 >> 6;
        int d = r2 & 63;
        g_fwt[r2] = (d < DVAR) ? fW[d*HID + u] : 0.0f;
    }
    const int total2 = 3*512*128;
    for (int idx = blockIdx.x*blockDim.x + threadIdx.x; idx < total2;
         idx += gridDim.x*blockDim.x) {
        int l = idx >> 16;
        int r = idx & 65535;
        int j = r >> 7;
        int k = r & 127;
        int din = (l == 0) ? DVAR : HID;
        g_w16[idx] = __float2half((k < din) ? WIH[l][j*din + k] : 0.0f);
    }
    const int total3 = 45*2048;
    for (int e = blockIdx.x*blockDim.x + threadIdx.x; e < total3;
         e += gridDim.x*blockDim.x) {
        int ksg = e >> 11;
        int r   = e & 2047;
        int n   = r >> 2;
        int q   = r & 3;
        unsigned short h4[4];
#pragma unroll
        for (int i = 0; i < 4; i++) {
            float v = 0.0f;
            if (ksg < 44) {
                int dl, ksl, kin, din;
                if (ksg < 12)      { dl = 0; ksl = ksg;      kin = 64;  din = DVAR; }
                else if (ksg < 28) { dl = 1; ksl = ksg - 12; kin = 128; din = HID; }
                else               { dl = 2; ksl = ksg - 28; kin = 128; din = HID; }
                int k = ksl*16 + q*2 + (i & 1) + ((i >> 1) << 3);
                const float* Wx = (dl == 0) ? w3 : (dl == 1) ? w4 : w5;
                const float* Wh = (dl == 0) ? u3 : (dl == 1) ? u4 : u5;
                if (k < kin) v = (k < din) ? Wx[n*din + k] : 0.0f;
                else         v = Wh[n*HID + (k - kin)];
            }
            h4[i] = __half_as_ushort(__float2half(v));
        }
        uint2 pk;
        pk.x = (uint32_t)h4[0] | ((uint32_t)h4[1] << 16);
        pk.y = (uint32_t)h4[2] | ((uint32_t)h4[3] << 16);
        g_wd[e] = pk;
    }
    const int total4 = 3*9*2048;
    for (int e = blockIdx.x*blockDim.x + threadIdx.x; e < total4;
         e += gridDim.x*blockDim.x) {
        int l   = e / (9*2048);
        int r0  = e - l*(9*2048);
        int ksg = r0 >> 11;
        int r   = r0 & 2047;
        int n   = r >> 2;
        int q   = r & 3;
        const float* Uh = (l == 0) ? u0 : (l == 1) ? u1 : u2;
        unsigned short h4[4];
#pragma unroll
        for (int i = 0; i < 4; i++) {
            float v = 0.0f;
            if (ksg < 8) {
                int k = ksg*16 + q*2 + (i & 1) + ((i >> 1) << 3);
                v = Uh[n*HID + k];
            }
            h4[i] = __half_as_ushort(__float2half(v));
        }
        uint2 pk;
        pk.x = (uint32_t)h4[0] | ((uint32_t)h4[1] << 16);
        pk.y = (uint32_t)h4[2] | ((uint32_t)h4[3] << 16);
        g_we[e] = pk;
    }
}

// ---------------------------------------------------------------------------
// Gx GEMM (HMMA, fp16 in/out) — unchanged from R15 (validated).
// ---------------------------------------------------------------------------
template<int KT, int MODE>
__global__ void __launch_bounds__(256, 2) gx_kernel(const float* __restrict__ src)
{
    extern __shared__ __half smh[];
    constexpr int SA = KT + 8;
    __half* As = smh;
    __half* Bs = smh + 128*SA;
    const int tid  = threadIdx.x;
    const int wid  = tid >> 5, lane = tid & 31;
    const int nb   = blockIdx.x * 128;
    const int m0   = blockIdx.y * 128;

    if (MODE == 0) {
        for (int idx = tid; idx < 128*KT; idx += 256) {
            int r = idx / KT, k = idx - r*KT;
            int m = m0 + r, b = m & (BATCH-1), t = m >> 11;
            float v = (k < DVAR) ? src[(b*TSEQ + t)*DVAR + k] : 0.0f;
            As[r*SA + k] = __float2half(v);
        }
    } else {
        for (int idx = tid; idx < 128*(KT/8); idx += 256) {
            int r  = idx / (KT/8);
            int k8 = idx - r*(KT/8);
            uint4 v = *(const uint4*)(g_hseq + (size_t)(m0 + r)*HID + k8*8);
            *(uint4*)(As + r*SA + k8*8) = v;
        }
    }
    {
        const int L = (MODE == 0) ? 0 : MODE;
        const uint4* ws = (const uint4*)(g_w16 + ((size_t)L*512 + nb)*128);
        for (int idx = tid; idx < 128*(KT/8); idx += 256) {
            int r  = idx / (KT/8);
            int k8 = idx - r*(KT/8);
            *(uint4*)(Bs + r*SA + k8*8) = ws[r*16 + k8];
        }
    }
    __syncthreads();

    float acc[16][4];
#pragma unroll
    for (int i = 0; i < 16; i++)
#pragma unroll
        for (int q = 0; q < 4; q++) acc[i][q] = 0.0f;

    const uint32_t rsel = (lane & 15);
    const uint32_t csel = (uint32_t)(lane >> 4) * 8;
    const uint32_t aaddr = smem_u32(As) + (((uint32_t)wid*16 + rsel)*SA + csel)*2;
    const uint32_t baddr = smem_u32(Bs) + (rsel*SA + csel)*2;

#pragma unroll
    for (int ks = 0; ks < KT/16; ks++) {
        uint32_t a0, a1, a2, a3;
        ldsm4(a0, a1, a2, a3, aaddr + ks*32);
#pragma unroll
        for (int np = 0; np < 8; np++) {
            uint32_t b0, b1, b2, b3;
            ldsm4(b0, b1, b2, b3, baddr + (uint32_t)np*16*SA*2 + ks*32);
            mma16816(acc[2*np    ], a0, a1, a2, a3, b0, b2);
            mma16816(acc[2*np + 1], a0, a1, a2, a3, b1, b3);
        }
    }

    const int mrow = m0 + wid*16 + (lane >> 2);
    __half* op  = g_gx + (size_t)mrow*G4 + nb + (lane & 3)*2;
    __half* op2 = op + 8*(size_t)G4;
#pragma unroll
    for (int nt = 0; nt < 16; nt++) {
        *(__half2*)(op  + nt*8) = __floats2half2_rn(acc[nt][0], acc[nt][1]);
        *(__half2*)(op2 + nt*8) = __floats2half2_rn(acc[nt][2], acc[nt][3]);
    }
}

// ---------------------------------------------------------------------------
// HMMA GEMM (M=16), B streamed from L2 (decoder).
// ---------------------------------------------------------------------------
template<int KS, int SA>
__device__ __forceinline__ void dec_gemm(char* smem, uint32_t ahi_off,
                                         uint32_t alo_off, uint32_t gates_off,
                                         const uint2* __restrict__ wd, int tid)
{
    const int lane  = tid & 31;
    const int wbase = (tid >> 5) * 4;

    float acc[16];
#pragma unroll
    for (int i = 0; i < 16; i++) acc[i] = 0.0f;

    const uint2* bp = wd + wbase*32 + lane;
    uint2 bc[4];
#pragma unroll
    for (int nt = 0; nt < 4; nt++) bc[nt] = bp[nt*32];

    const uint32_t abase = smem_u32(smem) + ((lane & 15)*SA + (lane >> 4)*8)*2;
    const uint32_t ahi = abase + ahi_off;
    const uint32_t alo = abase + alo_off;

#pragma unroll
    for (int ks = 0; ks < KS; ks++) {
        uint2 bn[4];
#pragma unroll
        for (int nt = 0; nt < 4; nt++) bn[nt] = bp[(ks + 1)*2048 + nt*32];
        uint32_t ah0, ah1, ah2, ah3, al0, al1, al2, al3;
        ldsm4(ah0, ah1, ah2, ah3, ahi + ks*32);
        ldsm4(al0, al1, al2, al3, alo + ks*32);
#pragma unroll
        for (int nt = 0; nt < 4; nt++) {
            mma16816(acc + nt*4, ah0, ah1, ah2, ah3, bc[nt].x, bc[nt].y);
            mma16816(acc + nt*4, al0, al1, al2, al3, bc[nt].x, bc[nt].y);
        }
#pragma unroll
        for (int nt = 0; nt < 4; nt++) bc[nt] = bn[nt];
    }

    float* gates = (float*)(smem + gates_off);
    const int row0 = lane >> 2;
    const int colb = wbase*8 + (lane & 3)*2;
#pragma unroll
    for (int nt = 0; nt < 4; nt++)
#pragma unroll
        for (int q = 0; q < 2; q++)
            *(float2*)(gates + (row0 + q*8)*520 + colb + nt*8)
                = make_float2(acc[nt*4 + 2*q], acc[nt*4 + 2*q + 1]);
}

// ---------------------------------------------------------------------------
// Encoder recurrent kernel: Whh B-fragments REGISTER-RESIDENT across the
// whole time loop (zero per-timestep weight traffic).
// ---------------------------------------------------------------------------
__global__ void __launch_bounds__(512, 1) rec_kernel(
    int layer, const float* __restrict__ bias, int writeseq)
{
    extern __shared__ char smem[];
    const int tid = threadIdx.x;
    const int b0  = blockIdx.x * RPB;
    const int lane  = tid & 31;
    const int wbase = (tid >> 5) * 4;

    for (int i = tid; i < 2176; i += 512) ((uint32_t*)(smem + RE_AHI))[i] = 0u;
    for (int i = tid; i < 2112; i += 512) ((uint32_t*)(smem + RE_C  ))[i] = 0u;
    ((float*)(smem + RE_BIAS))[tid] = bias[tid];

    // load Whh B fragments into registers once (32 uint2 = 64 regs)
    const uint2* bp = g_we + layer*9*2048 + wbase*32 + lane;
    uint2 bw[8][4];
#pragma unroll
    for (int ks = 0; ks < 8; ks++)
#pragma unroll
        for (int nt = 0; nt < 4; nt++)
            bw[ks][nt] = bp[ks*2048 + nt*32];
    __syncthreads();

    float* gates = (float*)(smem + RE_GATES);
    float* cb    = (float*)(smem + RE_C);
    const float* bias_s = (const float*)(smem + RE_BIAS);

    const uint32_t abase = smem_u32(smem) + ((lane & 15)*136 + (lane >> 4)*8)*2;
    const uint32_t ahi = abase + RE_AHI;
    const uint32_t alo = abase + RE_ALO;
    const int row0 = lane >> 2;
    const int colb = wbase*8 + (lane & 3)*2;

    for (int t = 0; t < TSEQ; t++) {
        // GEMM: gates[16][512] = A(hi+lo) @ Whh(regs)
        {
            float acc[16];
#pragma unroll
            for (int i = 0; i < 16; i++) acc[i] = 0.0f;
#pragma unroll
            for (int ks = 0; ks < 8; ks++) {
                uint32_t ah0, ah1, ah2, ah3, al0, al1, al2, al3;
                ldsm4(ah0, ah1, ah2, ah3, ahi + ks*32);
                ldsm4(al0, al1, al2, al3, alo + ks*32);
#pragma unroll
                for (int nt = 0; nt < 4; nt++) {
                    mma16816(acc + nt*4, ah0, ah1, ah2, ah3, bw[ks][nt].x, bw[ks][nt].y);
                    mma16816(acc + nt*4, al0, al1, al2, al3, bw[ks][nt].x, bw[ks][nt].y);
                }
            }
#pragma unroll
            for (int nt = 0; nt < 4; nt++)
#pragma unroll
                for (int q = 0; q < 2; q++)
                    *(float2*)(gates + (row0 + q*8)*520 + colb + nt*8)
                        = make_float2(acc[nt*4 + 2*q], acc[nt*4 + 2*q + 1]);
        }
        __syncthreads();

#pragma unroll
        for (int it = 0; it < 4; it++) {
            int idx = tid + it*512;
            if (idx < 14*128) {
                int r = idx >> 7, u = idx & 127;
                int b = b0 + r; if (b >= BATCH) b = BATCH - 1;
                const __half* gx = g_gx + ((size_t)t*BATCH + b)*G4;
                float gi = gates[r*520 + u      ] + bias_s[u      ] + __half2float(gx[u      ]);
                float gf = gates[r*520 + u + 128] + bias_s[u + 128] + __half2float(gx[u + 128]);
                float gg = gates[r*520 + u + 256] + bias_s[u + 256] + __half2float(gx[u + 256]);
                float go = gates[r*520 + u + 384] + bias_s[u + 384] + __half2float(gx[u + 384]);
                float cv = sigf(gf)*cb[r*132 + u] + sigf(gi)*tanhff(gg);
                cb[r*132 + u] = cv;
                float hn = sigf(go)*tanhff(cv);
                __half hh = __float2half(hn);
                __half hl = __float2half(hn - __half2float(hh));
                ((__half*)(smem + RE_AHI))[r*136 + u] = hh;
                ((__half*)(smem + RE_ALO))[r*136 + u] = hl;
                if (writeseq)
                    g_hseq[((size_t)t*BATCH + b)*HID + u] = hh;
                if (t == TSEQ - 1) {
                    g_state[(layer    )*BATCH*HID + b*HID + u] = hn;
                    g_state[(3 + layer)*BATCH*HID + b*HID + u] = cv;
                }
            }
        }
        __syncthreads();
    }
}

// Decoder elementwise for layer L (validated).
template<int L>
__device__ __forceinline__ void dec_ew(char* smem, int tid)
{
    constexpr int SA_SELF  = (L == 0) ? 200 : 264;
    constexpr int KIN      = (L == 0) ? 64 : 128;
    constexpr uint32_t AHI = (L == 0) ? OFF_A0H : (L == 1) ? OFF_A1H : OFF_A2H;
    constexpr uint32_t ALO = AHI + ((L == 0) ? 6400u : 8448u);
    constexpr uint32_t NHI = (L == 0) ? OFF_A1H : OFF_A2H;
    constexpr uint32_t NLO = NHI + 8448u;

    float* gates = (float*)(smem + OFF_GATES);
    const float* bias = (const float*)(smem + OFF_BIAS) + L*512;
    float* cb = (float*)(smem + OFF_C0 + L*8448u);
#pragma unroll
    for (int it = 0; it < 4; it++) {
        int idx = tid + it*512;
        if (idx < 14*128) {
            int r = idx >> 7, u = idx & 127;
            float gi = gates[r*520 + u      ] + bias[u      ];
            float gf = gates[r*520 + u + 128] + bias[u + 128];
            float gg = gates[r*520 + u + 256] + bias[u + 256];
            float go = gates[r*520 + u + 384] + bias[u + 384];
            float cv = sigf(gf)*cb[r*132 + u] + sigf(gi)*tanhff(gg);
            cb[r*132 + u] = cv;
            float hn = sigf(go)*tanhff(cv);
            __half hh = __float2half(hn);
            __half hl = __float2half(hn - __half2float(hh));
            ((__half*)(smem + AHI))[r*SA_SELF + KIN + u] = hh;
            ((__half*)(smem + ALO))[r*SA_SELF + KIN + u] = hl;
            if (L < 2) {
                ((__half*)(smem + NHI))[r*264 + u] = hh;
                ((__half*)(smem + NLO))[r*264 + u] = hl;
            } else {
                ((float*)(smem + OFF_H2))[r*132 + u] = hn;
            }
        }
    }
}

// ---------------------------------------------------------------------------
// Decoder persistent kernel (validated R13/R15 version).
// ---------------------------------------------------------------------------
__global__ void __launch_bounds__(512, 1) dec_kernel(
    const float* __restrict__ db0, const float* __restrict__ db1,
    const float* __restrict__ db2, const float* __restrict__ fb,
    float* __restrict__ out)
{
    extern __shared__ char smem[];
    const int tid = threadIdx.x;
    const int b0  = blockIdx.x * RPB;

    for (int i = tid; i < 11648; i += 512)
        ((uint32_t*)(smem + OFF_A0H))[i] = 0u;
    for (int i = tid; i < FWT_FLOATS; i += 512)
        ((float*)(smem + OFF_FWT))[i] = g_fwt[i];
    {
        float* bias = (float*)(smem + OFF_BIAS);
        bias[tid]        = db0[tid];
        bias[512 + tid]  = db1[tid];
        bias[1024 + tid] = db2[tid];
    }
    __syncthreads();

    for (int i = tid; i < 3*14*128; i += 512) {
        int u = i & 127;
        int r = (i >> 7) % 14;
        int l = i / (14*128);
        int b = b0 + r; if (b >= BATCH) b = BATCH - 1;
        float hv = g_state[l*BATCH*HID + b*HID + u];
        float cv = g_state[(3 + l)*BATCH*HID + b*HID + u];
        __half hh = __float2half(hv);
        __half hl = __float2half(hv - __half2float(hh));
        uint32_t ahi = (l == 0) ? OFF_A0H : (l == 1) ? OFF_A1H : OFF_A2H;
        uint32_t alo = ahi + ((l == 0) ? 6400u : 8448u);
        int sa  = (l == 0) ? 200 : 264;
        int kin = (l == 0) ? 64 : 128;
        ((__half*)(smem + ahi))[r*sa + kin + u] = hh;
        ((__half*)(smem + alo))[r*sa + kin + u] = hl;
        ((float*)(smem + OFF_C0 + (uint32_t)l*8448u))[r*132 + u] = cv;
    }
    __syncthreads();

    const float* fwts = (const float*)(smem + OFF_FWT);

    for (int t = 0; t < TSEQ; t++) {
        dec_gemm<12, 200>(smem, OFF_A0H, OFF_A0L, OFF_GATES, g_wd,           tid);
        __syncthreads();
        dec_ew<0>(smem, tid);
        __syncthreads();
        dec_gemm<16, 264>(smem, OFF_A1H, OFF_A1L, OFF_GATES, g_wd + 12*2048, tid);
        __syncthreads();
        dec_ew<1>(smem, tid);
        __syncthreads();
        dec_gemm<16, 264>(smem, OFF_A2H, OFF_A2L, OFF_GATES, g_wd + 28*2048, tid);
        __syncthreads();
        dec_ew<2>(smem, tid);
        __syncthreads();

        {
            int d  = tid & 63;
            int rg = tid >> 6;
            const float* h2 = (const float*)(smem + OFF_H2);
            float fbv = (d < DVAR) ? fb[d] : 0.0f;
            float a0 = fbv, a1 = fbv;
            int r0 = rg, r1 = rg + 8;
#pragma unroll 4
            for (int u = 0; u < HID; u++) {
                float wv = fwts[(u << 6) + d];
                a0 += h2[r0*132 + u] * wv;
                a1 += h2[r1*132 + u] * wv;
            }
            if (d < DVAR) {
                __half* xh = (__half*)(smem + OFF_A0H);
                __half* xl = (__half*)(smem + OFF_A0L);
                __half p0 = __float2half(a0);
                xh[r0*200 + d] = p0;
                xl[r0*200 + d] = __float2half(a0 - __half2float(p0));
                int bb = b0 + r0;
                if (bb < BATCH)
                    out[(bb*TSEQ + (TSEQ - 1 - t))*DVAR + d] = a0;
                if (r1 < RPB) {
                    __half p1 = __float2half(a1);
                    xh[r1*200 + d] = p1;
                    xl[r1*200 + d] = __float2half(a1 - __half2float(p1));
                    int bb1 = b0 + r1;
                    if (bb1 < BATCH)
                        out[(bb1*TSEQ + (TSEQ - 1 - t))*DVAR + d] = a1;
                }
            }
        }
        __syncthreads();
    }
}

// ---------------------------------------------------------------------------
extern "C" void kernel_launch(void* const* d_in, const int* in_sizes, int n_in,
                              void* d_out, int out_size)
{
    const float* src = (const float*)d_in[0];
    const float* eW0 = (const float*)d_in[1];
    const float* eU0 = (const float*)d_in[2];
    const float* eb0 = (const float*)d_in[3];
    const float* eW1 = (const float*)d_in[4];
    const float* eU1 = (const float*)d_in[5];
    const float* eb1 = (const float*)d_in[6];
    const float* eW2 = (const float*)d_in[7];
    const float* eU2 = (const float*)d_in[8];
    const float* eb2 = (const float*)d_in[9];
    const float* dW0 = (const float*)d_in[10];
    const float* dU0 = (const float*)d_in[11];
    const float* db0 = (const float*)d_in[12];
    const float* dW1 = (const float*)d_in[13];
    const float* dU1 = (const float*)d_in[14];
    const float* db1 = (const float*)d_in[15];
    const float* dW2 = (const float*)d_in[16];
    const float* dU2 = (const float*)d_in[17];
    const float* db2 = (const float*)d_in[18];
    const float* fW  = (const float*)d_in[19];
    const float* fb  = (const float*)d_in[20];
    float* out = (float*)d_out;

    const int GX64_SMEM  = 2*128*(64 + 8)*2;
    const int GX128_SMEM = 2*128*(128 + 8)*2;

    cudaFuncSetAttribute(gx_kernel<64,0>,  cudaFuncAttributeMaxDynamicSharedMemorySize, GX64_SMEM);
    cudaFuncSetAttribute(gx_kernel<128,1>, cudaFuncAttributeMaxDynamicSharedMemorySize, GX128_SMEM);
    cudaFuncSetAttribute(gx_kernel<128,2>, cudaFuncAttributeMaxDynamicSharedMemorySize, GX128_SMEM);
    cudaFuncSetAttribute(rec_kernel, cudaFuncAttributeMaxDynamicSharedMemorySize, RE_SMEM);
    cudaFuncSetAttribute(dec_kernel, cudaFuncAttributeMaxDynamicSharedMemorySize, DEC_SMEM);

    prep_kernel<<<1024, 256>>>(eW0, eU0, eW1, eU1, eW2, eU2,
                               dW0, dU0, dW1, dU1, dW2, dU2, fW);

    dim3 gxgrid(4, 1600);
    gx_kernel<64,0><<<gxgrid, 256, GX64_SMEM>>>(src);
    rec_kernel<<<NBLK, 512, RE_SMEM>>>(0, eb0, 1);
    gx_kernel<128,1><<<gxgrid, 256, GX128_SMEM>>>(src);
    rec_kernel<<<NBLK, 512, RE_SMEM>>>(1, eb1, 1);
    gx_kernel<128,2><<<gxgrid, 256, GX128_SMEM>>>(src);
    rec_kernel<<<NBLK, 512, RE_SMEM>>>(2, eb2, 0);
    dec_kernel<<<NBLK, 512, DEC_SMEM>>>(db0, db1, db2, fb, out);
}

// round 17
// speedup vs baseline: 2.2429x; 1.1522x over previous
#include <cuda_runtime.h>
#include <cuda_fp16.h>
#include <cstdint>

#define BATCH 2048
#define TSEQ  100
#define DVAR  51
#define HID   128
#define G4    512
#define RPB   14
#define NBLK  147

#define FWT_FLOATS (128*64)

// ---- decoder smem map (bytes) ----
#define OFF_FWT   0u
#define OFF_BIAS  32768u
#define OFF_A0H   38912u
#define OFF_A0L   45312u
#define OFF_A1H   51712u
#define OFF_A1L   60160u
#define OFF_A2H   68608u
#define OFF_A2L   77056u
#define OFF_GATES 85504u
#define OFF_C0    118784u
#define OFF_H2    144128u
#define DEC_SMEM  152576

// ---- fused encoder smem map (bytes) ----
#define EA0H   0u          /* 16*136 h = 4352 */
#define EA0L   4352u
#define EA1H   8704u       /* 16*264 h = 8448 */
#define EA1L   17152u
#define EA2H   25600u
#define EA2L   34048u
#define EGATES 42496u      /* 16*520 f32 = 33280 */
#define EC     75776u      /* 3 * 14*128 f32 = 21504 */
#define EBIAS  97280u      /* 3*512 f32 = 6144 */
#define ENC_SMEM 103424

// ---------------- device scratch ----------------
__device__ float  g_fwt[FWT_FLOATS];
__device__ __half g_gx[(size_t)TSEQ*BATCH*G4];   // layer-0 x-projection only
__device__ float  g_state[6*BATCH*HID];
__device__ __half g_w16[512*128];                // Wih layer 0 fp16 image
__device__ uint2  g_wd[46*2048];                 // decoder pack (+2 pad groups)
__device__ uint2  g_we2[42*2048];                // enc pack: Whh0(8) | W1(16) | W2(16) | pad(2)

__device__ __forceinline__ float sigf(float x) {
    return __fdividef(1.0f, 1.0f + __expf(-x));
}
__device__ __forceinline__ float tanhff(float x) {
    float e = __expf(2.0f * x);
    return 1.0f - __fdividef(2.0f, e + 1.0f);
}
__device__ __forceinline__ uint32_t smem_u32(const void* p) {
    uint32_t a;
    asm("{ .reg .u64 t; cvta.to.shared.u64 t, %1; cvt.u32.u64 %0, t; }" : "=r"(a) : "l"(p));
    return a;
}
__device__ __forceinline__ void ldsm4(uint32_t& r0, uint32_t& r1,
                                      uint32_t& r2, uint32_t& r3, uint32_t a) {
    asm volatile("ldmatrix.sync.aligned.m8n8.x4.shared.b16 {%0,%1,%2,%3}, [%4];"
                 : "=r"(r0), "=r"(r1), "=r"(r2), "=r"(r3) : "r"(a));
}
__device__ __forceinline__ void mma16816(float* d,
                                         uint32_t a0, uint32_t a1, uint32_t a2, uint32_t a3,
                                         uint32_t b0, uint32_t b1) {
    asm volatile(
        "mma.sync.aligned.m16n8k16.row.col.f32.f16.f16.f32 "
        "{%0,%1,%2,%3}, {%4,%5,%6,%7}, {%8,%9}, {%0,%1,%2,%3};"
        : "+f"(d[0]), "+f"(d[1]), "+f"(d[2]), "+f"(d[3])
        : "r"(a0), "r"(a1), "r"(a2), "r"(a3), "r"(b0), "r"(b1));
}

// ---------------------------------------------------------------------------
// Prep: fW^T, layer-0 Wih fp16 image, decoder pack, fused-encoder pack.
// Fragment formula identical to the validated R13 packer.
// ---------------------------------------------------------------------------
__global__ void prep_kernel(
    const float* w0, const float* u0, const float* w1, const float* u1,
    const float* w2, const float* u2, const float* w3, const float* u3,
    const float* w4, const float* u4, const float* w5, const float* u5,
    const float* fW)
{
    for (int r2 = blockIdx.x*blockDim.x + threadIdx.x; r2 < FWT_FLOATS;
         r2 += gridDim.x*blockDim.x) {
        int u = r2 >> 6;
        int d = r2 & 63;
        g_fwt[r2] = (d < DVAR) ? fW[d*HID + u] : 0.0f;
    }
    // layer-0 Wih image [j 0..511][k 0..127]
    for (int idx = blockIdx.x*blockDim.x + threadIdx.x; idx < 512*128;
         idx += gridDim.x*blockDim.x) {
        int j = idx >> 7;
        int k = idx & 127;
        g_w16[idx] = __float2half((k < DVAR) ? w0[j*DVAR + k] : 0.0f);
    }
    // decoder pack (46 groups, 44 real)
    const int total3 = 46*2048;
    for (int e = blockIdx.x*blockDim.x + threadIdx.x; e < total3;
         e += gridDim.x*blockDim.x) {
        int ksg = e >> 11;
        int r   = e & 2047;
        int n   = r >> 2;
        int q   = r & 3;
        unsigned short h4[4];
#pragma unroll
        for (int i = 0; i < 4; i++) {
            float v = 0.0f;
            if (ksg < 44) {
                int dl, ksl, kin, din;
                if (ksg < 12)      { dl = 0; ksl = ksg;      kin = 64;  din = DVAR; }
                else if (ksg < 28) { dl = 1; ksl = ksg - 12; kin = 128; din = HID; }
                else               { dl = 2; ksl = ksg - 28; kin = 128; din = HID; }
                int k = ksl*16 + q*2 + (i & 1) + ((i >> 1) << 3);
                const float* Wx = (dl == 0) ? w3 : (dl == 1) ? w4 : w5;
                const float* Wh = (dl == 0) ? u3 : (dl == 1) ? u4 : u5;
                if (k < kin) v = (k < din) ? Wx[n*din + k] : 0.0f;
                else         v = Wh[n*HID + (k - kin)];
            }
            h4[i] = __half_as_ushort(__float2half(v));
        }
        uint2 pk;
        pk.x = (uint32_t)h4[0] | ((uint32_t)h4[1] << 16);
        pk.y = (uint32_t)h4[2] | ((uint32_t)h4[3] << 16);
        g_wd[e] = pk;
    }
    // fused-encoder pack: groups [0,8)=Whh0 (K=128), [8,24)=[Wih1;Whh1],
    // [24,40)=[Wih2;Whh2], [40,42)=zero pad
    const int total5 = 42*2048;
    for (int e = blockIdx.x*blockDim.x + threadIdx.x; e < total5;
         e += gridDim.x*blockDim.x) {
        int g = e >> 11;
        int r = e & 2047;
        int n = r >> 2;
        int q = r & 3;
        unsigned short h4[4];
#pragma unroll
        for (int i = 0; i < 4; i++) {
            float v = 0.0f;
            if (g < 8) {
                int k = g*16 + q*2 + (i & 1) + ((i >> 1) << 3);
                v = u0[n*HID + k];
            } else if (g < 40) {
                int layer1 = (g < 24);
                int ksl = g - (layer1 ? 8 : 24);
                int k = ksl*16 + q*2 + (i & 1) + ((i >> 1) << 3);
                const float* Wx = layer1 ? w1 : w2;
                const float* Wh = layer1 ? u1 : u2;
                v = (k < 128) ? Wx[n*HID + k] : Wh[n*HID + (k - 128)];
            }
            h4[i] = __half_as_ushort(__float2half(v));
        }
        uint2 pk;
        pk.x = (uint32_t)h4[0] | ((uint32_t)h4[1] << 16);
        pk.y = (uint32_t)h4[2] | ((uint32_t)h4[3] << 16);
        g_we2[e] = pk;
    }
}

// ---------------------------------------------------------------------------
// Gx GEMM (HMMA, layer 0 only): gx = src @ Wih0^T, fp16 out. Validated.
// ---------------------------------------------------------------------------
__global__ void __launch_bounds__(256, 2) gx_kernel(const float* __restrict__ src)
{
    extern __shared__ __half smh[];
    constexpr int KT = 64;
    constexpr int SA = KT + 8;
    __half* As = smh;
    __half* Bs = smh + 128*SA;
    const int tid  = threadIdx.x;
    const int wid  = tid >> 5, lane = tid & 31;
    const int nb   = blockIdx.x * 128;
    const int m0   = blockIdx.y * 128;

    for (int idx = tid; idx < 128*KT; idx += 256) {
        int r = idx / KT, k = idx - r*KT;
        int m = m0 + r, b = m & (BATCH-1), t = m >> 11;
        float v = (k < DVAR) ? src[(b*TSEQ + t)*DVAR + k] : 0.0f;
        As[r*SA + k] = __float2half(v);
    }
    {
        const uint4* ws = (const uint4*)(g_w16 + (size_t)nb*128);
        for (int idx = tid; idx < 128*(KT/8); idx += 256) {
            int r  = idx / (KT/8);
            int k8 = idx - r*(KT/8);
            *(uint4*)(Bs + r*SA + k8*8) = ws[r*16 + k8];
        }
    }
    __syncthreads();

    float acc[16][4];
#pragma unroll
    for (int i = 0; i < 16; i++)
#pragma unroll
        for (int q = 0; q < 4; q++) acc[i][q] = 0.0f;

    const uint32_t rsel = (lane & 15);
    const uint32_t csel = (uint32_t)(lane >> 4) * 8;
    const uint32_t aaddr = smem_u32(As) + (((uint32_t)wid*16 + rsel)*SA + csel)*2;
    const uint32_t baddr = smem_u32(Bs) + (rsel*SA + csel)*2;

#pragma unroll
    for (int ks = 0; ks < KT/16; ks++) {
        uint32_t a0, a1, a2, a3;
        ldsm4(a0, a1, a2, a3, aaddr + ks*32);
#pragma unroll
        for (int np = 0; np < 8; np++) {
            uint32_t b0, b1, b2, b3;
            ldsm4(b0, b1, b2, b3, baddr + (uint32_t)np*16*SA*2 + ks*32);
            mma16816(acc[2*np    ], a0, a1, a2, a3, b0, b2);
            mma16816(acc[2*np + 1], a0, a1, a2, a3, b1, b3);
        }
    }

    const int mrow = m0 + wid*16 + (lane >> 2);
    __half* op  = g_gx + (size_t)mrow*G4 + nb + (lane & 3)*2;
    __half* op2 = op + 8*(size_t)G4;
#pragma unroll
    for (int nt = 0; nt < 16; nt++) {
        *(__half2*)(op  + nt*8) = __floats2half2_rn(acc[nt][0], acc[nt][1]);
        *(__half2*)(op2 + nt*8) = __floats2half2_rn(acc[nt][2], acc[nt][3]);
    }
}

// ---------------------------------------------------------------------------
// Streaming HMMA GEMM (M=16), B from L2 in fragment order, DEPTH-2 prefetch.
// ---------------------------------------------------------------------------
template<int KS, int SA>
__device__ __forceinline__ void sgemm(char* smem, uint32_t ahi_off,
                                      uint32_t alo_off, uint32_t gates_off,
                                      const uint2* __restrict__ wd, int tid)
{
    const int lane  = tid & 31;
    const int wbase = (tid >> 5) * 4;

    float acc[16];
#pragma unroll
    for (int i = 0; i < 16; i++) acc[i] = 0.0f;

    const uint2* bp = wd + wbase*32 + lane;
    uint2 bc[4], bn[4];
#pragma unroll
    for (int nt = 0; nt < 4; nt++) { bc[nt] = bp[nt*32]; bn[nt] = bp[2048 + nt*32]; }

    const uint32_t abase = smem_u32(smem) + ((lane & 15)*SA + (lane >> 4)*8)*2;
    const uint32_t ahi = abase + ahi_off;
    const uint32_t alo = abase + alo_off;

#pragma unroll
    for (int ks = 0; ks < KS; ks++) {
        uint2 b2[4];
#pragma unroll
        for (int nt = 0; nt < 4; nt++) b2[nt] = bp[(ks + 2)*2048 + nt*32]; // pad-safe
        uint32_t ah0, ah1, ah2, ah3, al0, al1, al2, al3;
        ldsm4(ah0, ah1, ah2, ah3, ahi + ks*32);
        ldsm4(al0, al1, al2, al3, alo + ks*32);
#pragma unroll
        for (int nt = 0; nt < 4; nt++) {
            mma16816(acc + nt*4, ah0, ah1, ah2, ah3, bc[nt].x, bc[nt].y);
            mma16816(acc + nt*4, al0, al1, al2, al3, bc[nt].x, bc[nt].y);
        }
#pragma unroll
        for (int nt = 0; nt < 4; nt++) { bc[nt] = bn[nt]; bn[nt] = b2[nt]; }
    }

    float* gates = (float*)(smem + gates_off);
    const int row0 = lane >> 2;
    const int colb = wbase*8 + (lane & 3)*2;
#pragma unroll
    for (int nt = 0; nt < 4; nt++)
#pragma unroll
        for (int q = 0; q < 2; q++)
            *(float2*)(gates + (row0 + q*8)*520 + colb + nt*8)
                = make_float2(acc[nt*4 + 2*q], acc[nt*4 + 2*q + 1]);
}

// ---------------------------------------------------------------------------
// Fused encoder elementwise for layer L.
//   L0: + gx from gmem; hn -> A0 (own recurrent) + A1 cols[0,128)
//   L1: hn -> A1 cols[128,256) + A2 cols[0,128)
//   L2: hn -> A2 cols[128,256); state at t==99 for all layers
// ---------------------------------------------------------------------------
template<int L>
__device__ __forceinline__ void enc_ew(char* smem, int tid, int t, int b0)
{
    float* gates = (float*)(smem + EGATES);
    const float* bias = (const float*)(smem + EBIAS) + L*512;
    float* cb = (float*)(smem + EC + (uint32_t)L*7168u);
#pragma unroll
    for (int it = 0; it < 4; it++) {
        int idx = tid + it*512;
        if (idx < 14*128) {
            int r = idx >> 7, u = idx & 127;
            int b = b0 + r; if (b >= BATCH) b = BATCH - 1;
            float gi = gates[r*520 + u      ] + bias[u      ];
            float gf = gates[r*520 + u + 128] + bias[u + 128];
            float gg = gates[r*520 + u + 256] + bias[u + 256];
            float go = gates[r*520 + u + 384] + bias[u + 384];
            if (L == 0) {
                const __half* gx = g_gx + ((size_t)t*BATCH + b)*G4;
                gi += __half2float(gx[u      ]);
                gf += __half2float(gx[u + 128]);
                gg += __half2float(gx[u + 256]);
                go += __half2float(gx[u + 384]);
            }
            float cv = sigf(gf)*cb[r*128 + u] + sigf(gi)*tanhff(gg);
            cb[r*128 + u] = cv;
            float hn = sigf(go)*tanhff(cv);
            __half hh = __float2half(hn);
            __half hl = __float2half(hn - __half2float(hh));
            if (L == 0) {
                ((__half*)(smem + EA0H))[r*136 + u] = hh;
                ((__half*)(smem + EA0L))[r*136 + u] = hl;
                ((__half*)(smem + EA1H))[r*264 + u] = hh;
                ((__half*)(smem + EA1L))[r*264 + u] = hl;
            } else if (L == 1) {
                ((__half*)(smem + EA1H))[r*264 + 128 + u] = hh;
                ((__half*)(smem + EA1L))[r*264 + 128 + u] = hl;
                ((__half*)(smem + EA2H))[r*264 + u] = hh;
                ((__half*)(smem + EA2L))[r*264 + u] = hl;
            } else {
                ((__half*)(smem + EA2H))[r*264 + 128 + u] = hh;
                ((__half*)(smem + EA2L))[r*264 + 128 + u] = hl;
            }
            if (t == TSEQ - 1) {
                g_state[(L    )*BATCH*HID + b*HID + u] = hn;
                g_state[(3 + L)*BATCH*HID + b*HID + u] = cv;
            }
        }
    }
}

// ---------------------------------------------------------------------------
// Fused encoder: all 3 layers per timestep in one persistent kernel.
// ---------------------------------------------------------------------------
__global__ void __launch_bounds__(512, 1) enc_kernel(
    const float* __restrict__ eb0, const float* __restrict__ eb1,
    const float* __restrict__ eb2)
{
    extern __shared__ char smem[];
    const int tid = threadIdx.x;
    const int b0  = blockIdx.x * RPB;

    // zero A buffers + c (bytes 0..42496 and EC..EC+21504)
    for (int i = tid; i < 10624; i += 512) ((uint32_t*)(smem))[i] = 0u;
    for (int i = tid; i < 5376;  i += 512) ((uint32_t*)(smem + EC))[i] = 0u;
    {
        float* bias = (float*)(smem + EBIAS);
        bias[tid]        = eb0[tid];
        bias[512 + tid]  = eb1[tid];
        bias[1024 + tid] = eb2[tid];
    }
    __syncthreads();

    for (int t = 0; t < TSEQ; t++) {
        sgemm<8, 136>(smem, EA0H, EA0L, EGATES, g_we2,           tid);
        __syncthreads();
        enc_ew<0>(smem, tid, t, b0);
        __syncthreads();
        sgemm<16, 264>(smem, EA1H, EA1L, EGATES, g_we2 + 8*2048, tid);
        __syncthreads();
        enc_ew<1>(smem, tid, t, b0);
        __syncthreads();
        sgemm<16, 264>(smem, EA2H, EA2L, EGATES, g_we2 + 24*2048, tid);
        __syncthreads();
        enc_ew<2>(smem, tid, t, b0);
        __syncthreads();
    }
}

// Decoder elementwise for layer L (validated).
template<int L>
__device__ __forceinline__ void dec_ew(char* smem, int tid)
{
    constexpr int SA_SELF  = (L == 0) ? 200 : 264;
    constexpr int KIN      = (L == 0) ? 64 : 128;
    constexpr uint32_t AHI = (L == 0) ? OFF_A0H : (L == 1) ? OFF_A1H : OFF_A2H;
    constexpr uint32_t ALO = AHI + ((L == 0) ? 6400u : 8448u);
    constexpr uint32_t NHI = (L == 0) ? OFF_A1H : OFF_A2H;
    constexpr uint32_t NLO = NHI + 8448u;

    float* gates = (float*)(smem + OFF_GATES);
    const float* bias = (const float*)(smem + OFF_BIAS) + L*512;
    float* cb = (float*)(smem + OFF_C0 + L*8448u);
#pragma unroll
    for (int it = 0; it < 4; it++) {
        int idx = tid + it*512;
        if (idx < 14*128) {
            int r = idx >> 7, u = idx & 127;
            float gi = gates[r*520 + u      ] + bias[u      ];
            float gf = gates[r*520 + u + 128] + bias[u + 128];
            float gg = gates[r*520 + u + 256] + bias[u + 256];
            float go = gates[r*520 + u + 384] + bias[u + 384];
            float cv = sigf(gf)*cb[r*132 + u] + sigf(gi)*tanhff(gg);
            cb[r*132 + u] = cv;
            float hn = sigf(go)*tanhff(cv);
            __half hh = __float2half(hn);
            __half hl = __float2half(hn - __half2float(hh));
            ((__half*)(smem + AHI))[r*SA_SELF + KIN + u] = hh;
            ((__half*)(smem + ALO))[r*SA_SELF + KIN + u] = hl;
            if (L < 2) {
                ((__half*)(smem + NHI))[r*264 + u] = hh;
                ((__half*)(smem + NLO))[r*264 + u] = hl;
            } else {
                ((float*)(smem + OFF_H2))[r*132 + u] = hn;
            }
        }
    }
}

// ---------------------------------------------------------------------------
// Decoder persistent kernel (validated; sgemm depth-2 now).
// ---------------------------------------------------------------------------
__global__ void __launch_bounds__(512, 1) dec_kernel(
    const float* __restrict__ db0, const float* __restrict__ db1,
    const float* __restrict__ db2, const float* __restrict__ fb,
    float* __restrict__ out)
{
    extern __shared__ char smem[];
    const int tid = threadIdx.x;
    const int b0  = blockIdx.x * RPB;

    for (int i = tid; i < 11648; i += 512)
        ((uint32_t*)(smem + OFF_A0H))[i] = 0u;
    for (int i = tid; i < FWT_FLOATS; i += 512)
        ((float*)(smem + OFF_FWT))[i] = g_fwt[i];
    {
        float* bias = (float*)(smem + OFF_BIAS);
        bias[tid]        = db0[tid];
        bias[512 + tid]  = db1[tid];
        bias[1024 + tid] = db2[tid];
    }
    __syncthreads();

    for (int i = tid; i < 3*14*128; i += 512) {
        int u = i & 127;
        int r = (i >> 7) % 14;
        int l = i / (14*128);
        int b = b0 + r; if (b >= BATCH) b = BATCH - 1;
        float hv = g_state[l*BATCH*HID + b*HID + u];
        float cv = g_state[(3 + l)*BATCH*HID + b*HID + u];
        __half hh = __float2half(hv);
        __half hl = __float2half(hv - __half2float(hh));
        uint32_t ahi = (l == 0) ? OFF_A0H : (l == 1) ? OFF_A1H : OFF_A2H;
        uint32_t alo = ahi + ((l == 0) ? 6400u : 8448u);
        int sa  = (l == 0) ? 200 : 264;
        int kin = (l == 0) ? 64 : 128;
        ((__half*)(smem + ahi))[r*sa + kin + u] = hh;
        ((__half*)(smem + alo))[r*sa + kin + u] = hl;
        ((float*)(smem + OFF_C0 + (uint32_t)l*8448u))[r*132 + u] = cv;
    }
    __syncthreads();

    const float* fwts = (const float*)(smem + OFF_FWT);

    for (int t = 0; t < TSEQ; t++) {
        sgemm<12, 200>(smem, OFF_A0H, OFF_A0L, OFF_GATES, g_wd,           tid);
        __syncthreads();
        dec_ew<0>(smem, tid);
        __syncthreads();
        sgemm<16, 264>(smem, OFF_A1H, OFF_A1L, OFF_GATES, g_wd + 12*2048, tid);
        __syncthreads();
        dec_ew<1>(smem, tid);
        __syncthreads();
        sgemm<16, 264>(smem, OFF_A2H, OFF_A2L, OFF_GATES, g_wd + 28*2048, tid);
        __syncthreads();
        dec_ew<2>(smem, tid);
        __syncthreads();

        {
            int d  = tid & 63;
            int rg = tid >> 6;
            const float* h2 = (const float*)(smem + OFF_H2);
            float fbv = (d < DVAR) ? fb[d] : 0.0f;
            float a0 = fbv, a1 = fbv;
            int r0 = rg, r1 = rg + 8;
#pragma unroll 4
            for (int u = 0; u < HID; u++) {
                float wv = fwts[(u << 6) + d];
                a0 += h2[r0*132 + u] * wv;
                a1 += h2[r1*132 + u] * wv;
            }
            if (d < DVAR) {
                __half* xh = (__half*)(smem + OFF_A0H);
                __half* xl = (__half*)(smem + OFF_A0L);
                __half p0 = __float2half(a0);
                xh[r0*200 + d] = p0;
                xl[r0*200 + d] = __float2half(a0 - __half2float(p0));
                int bb = b0 + r0;
                if (bb < BATCH)
                    out[(bb*TSEQ + (TSEQ - 1 - t))*DVAR + d] = a0;
                if (r1 < RPB) {
                    __half p1 = __float2half(a1);
                    xh[r1*200 + d] = p1;
                    xl[r1*200 + d] = __float2half(a1 - __half2float(p1));
                    int bb1 = b0 + r1;
                    if (bb1 < BATCH)
                        out[(bb1*TSEQ + (TSEQ - 1 - t))*DVAR + d] = a1;
                }
            }
        }
        __syncthreads();
    }
}

// ---------------------------------------------------------------------------
extern "C" void kernel_launch(void* const* d_in, const int* in_sizes, int n_in,
                              void* d_out, int out_size)
{
    const float* src = (const float*)d_in[0];
    const float* eW0 = (const float*)d_in[1];
    const float* eU0 = (const float*)d_in[2];
    const float* eb0 = (const float*)d_in[3];
    const float* eW1 = (const float*)d_in[4];
    const float* eU1 = (const float*)d_in[5];
    const float* eb1 = (const float*)d_in[6];
    const float* eW2 = (const float*)d_in[7];
    const float* eU2 = (const float*)d_in[8];
    const float* eb2 = (const float*)d_in[9];
    const float* dW0 = (const float*)d_in[10];
    const float* dU0 = (const float*)d_in[11];
    const float* db0 = (const float*)d_in[12];
    const float* dW1 = (const float*)d_in[13];
    const float* dU1 = (const float*)d_in[14];
    const float* db1 = (const float*)d_in[15];
    const float* dW2 = (const float*)d_in[16];
    const float* dU2 = (const float*)d_in[17];
    const float* db2 = (const float*)d_in[18];
    const float* fW  = (const float*)d_in[19];
    const float* fb  = (const float*)d_in[20];
    float* out = (float*)d_out;

    const int GX64_SMEM = 2*128*(64 + 8)*2;

    cudaFuncSetAttribute(gx_kernel,  cudaFuncAttributeMaxDynamicSharedMemorySize, GX64_SMEM);
    cudaFuncSetAttribute(enc_kernel, cudaFuncAttributeMaxDynamicSharedMemorySize, ENC_SMEM);
    cudaFuncSetAttribute(dec_kernel, cudaFuncAttributeMaxDynamicSharedMemorySize, DEC_SMEM);

    prep_kernel<<<1024, 256>>>(eW0, eU0, eW1, eU1, eW2, eU2,
                               dW0, dU0, dW1, dU1, dW2, dU2, fW);

    dim3 gxgrid(4, 1600);
    gx_kernel<<<gxgrid, 256, GX64_SMEM>>>(src);
    enc_kernel<<<NBLK, 512, ENC_SMEM>>>(eb0, eb1, eb2);
    dec_kernel<<<NBLK, 512, DEC_SMEM>>>(db0, db1, db2, fb, out);
}